// round 4
// baseline (speedup 1.0000x reference)
#include <cuda_runtime.h>
#include <math.h>

// LureSystem recurrence on GB300.
// 16 groups x 8-CTA clusters. Group g owns batches [16g, 16g+16).
// Cluster rank r owns rows [32r,32r+32) of w and x, rows [8r,8r+8) of e.
// Weight slices (130KB) resident in SMEM; x/w exchanged via L2 global buffers
// with st.cg/ld.cg + barrier.cluster (release/acquire) per phase.

#define NXd 256
#define NDd 64
#define NEd 64
#define NWd 256
#define NBATCH 256
#define NSTEPS 2048
#define RANKS 8
#define GROUPS 16
#define BT 16
#define THREADS 256

// padded strides (avoid stride % 32 == 0 bank degeneracy)
#define S_W1 321
#define S_W2 577
#define S_ACT 577
#define S_PAR 529

#define E_SIZE (NBATCH * NSTEPS * NEd)       // 33554432
#define BASE_X E_SIZE
#define BASE_W (E_SIZE + NBATCH * NXd)

// exchange buffers (per group): full w and full x_new vectors for the batch tile
__device__ float g_wbuf[GROUPS * BT * NWd];
__device__ float g_xbuf[GROUPS * BT * NXd];

__device__ __forceinline__ void cluster_sync_rel() {
    __threadfence();  // belt & braces: drain st.cg to L2 before release-arrive
    asm volatile("barrier.cluster.arrive.aligned;" ::: "memory");
    asm volatile("barrier.cluster.wait.aligned;" ::: "memory");
}

// Partial GEMM micro-kernel: NR rows x NB batches register tile over a
// JL-length K-chunk. W points at (row0, j0) of the weight slab (stride WS),
// Aact points at (b0, j0) of the activation slab (stride S_ACT).
// Writes NRxNB partials to P[kk*33 + i].
template <int JL, int WS, int NR, int NB>
__device__ __forceinline__ void mm_partial(const float* __restrict__ W,
                                           const float* __restrict__ Aact,
                                           float* __restrict__ P) {
    float acc[NR][NB];
#pragma unroll
    for (int i = 0; i < NR; i++)
#pragma unroll
        for (int kk = 0; kk < NB; kk++) acc[i][kk] = 0.f;

#pragma unroll 4
    for (int j = 0; j < JL; j++) {
        float m[NR];
#pragma unroll
        for (int i = 0; i < NR; i++) m[i] = W[i * WS + j];
#pragma unroll
        for (int kk = 0; kk < NB; kk++) {
            float a = Aact[kk * S_ACT + j];
#pragma unroll
            for (int i = 0; i < NR; i++) acc[i][kk] = fmaf(m[i], a, acc[i][kk]);
        }
    }
#pragma unroll
    for (int kk = 0; kk < NB; kk++)
#pragma unroll
        for (int i = 0; i < NR; i++) P[kk * 33 + i] = acc[i][kk];
}

__global__ void __cluster_dims__(RANKS, 1, 1) __launch_bounds__(THREADS, 1)
lure_kernel(const float* __restrict__ dseq,
            const float* __restrict__ x0,
            const float* __restrict__ Amat,
            const float* __restrict__ Bmat,
            const float* __restrict__ B2mat,
            const float* __restrict__ Cmat,
            const float* __restrict__ Dmat,
            const float* __restrict__ D12mat,
            const float* __restrict__ C2mat,
            const float* __restrict__ D21mat,
            float* __restrict__ out) {
    extern __shared__ float smem[];
    // SMEM layout (floats):
    float* sW1  = smem;                    // [32][S_W1]  = [C2 | D21]   (K=320)
    float* sW2  = sW1 + 32 * S_W1;         // [32][S_W2]  = [A | B | B2] (K=576)
    float* sW3  = sW2 + 32 * S_W2;         // [8][S_W2]   = [C | D | D12]
    float* sAct = sW3 + 8 * S_W2;          // [16][S_ACT] = [x(256) | d(64) | w(256)]
    float* sPar = sAct + BT * S_ACT;       // [16][S_PAR] partial sums

    const int t = threadIdx.x;
    const int g = blockIdx.x >> 3;         // group id (0..15)
    const int r = blockIdx.x & 7;          // cluster rank (0..7)
    const int rw = r * 32;                 // w/x row base
    const int re = r * 8;                  // e row base

    // ---- load resident weight slices ----
    for (int idx = t; idx < 32 * 256; idx += THREADS) {
        int row = idx >> 8, col = idx & 255;
        sW1[row * S_W1 + col] = C2mat[(rw + row) * NXd + col];
    }
    for (int idx = t; idx < 32 * 64; idx += THREADS) {
        int row = idx >> 6, col = idx & 63;
        sW1[row * S_W1 + 256 + col] = D21mat[(rw + row) * NDd + col];
    }
    for (int idx = t; idx < 32 * 256; idx += THREADS) {
        int row = idx >> 8, col = idx & 255;
        sW2[row * S_W2 + col] = Amat[(rw + row) * NXd + col];
    }
    for (int idx = t; idx < 32 * 64; idx += THREADS) {
        int row = idx >> 6, col = idx & 63;
        sW2[row * S_W2 + 256 + col] = Bmat[(rw + row) * NDd + col];
    }
    for (int idx = t; idx < 32 * 256; idx += THREADS) {
        int row = idx >> 8, col = idx & 255;
        sW2[row * S_W2 + 320 + col] = B2mat[(rw + row) * NWd + col];
    }
    for (int idx = t; idx < 8 * 256; idx += THREADS) {
        int row = idx >> 8, col = idx & 255;
        sW3[row * S_W2 + col] = Cmat[(re + row) * NXd + col];
    }
    for (int idx = t; idx < 8 * 64; idx += THREADS) {
        int row = idx >> 6, col = idx & 63;
        sW3[row * S_W2 + 256 + col] = Dmat[(re + row) * NDd + col];
    }
    for (int idx = t; idx < 8 * 256; idx += THREADS) {
        int row = idx >> 8, col = idx & 255;
        sW3[row * S_W2 + 320 + col] = D12mat[(re + row) * NWd + col];
    }
    // initial state x0 into act x-part
    for (int idx = t; idx < BT * 256; idx += THREADS) {
        int b = idx >> 8, col = idx & 255;
        sAct[b * S_ACT + col] = x0[(g * BT + b) * NXd + col];
    }

    // work decomposition
    const int lane = t & 31, warp = t >> 5;
    const int chunk = warp * 2 + (lane >> 4);   // 16 K-chunks
    const int tile = lane & 15;
    const int row0 = (tile & 7) * 4;            // w/x: 4 rows x 8 batches per lane
    const int b0 = (tile >> 3) * 8;
    const int rowe0 = (tile & 3) * 2;           // e: 2 rows x 4 batches per lane
    const int be0 = (tile >> 2) * 4;

    float* gw = g_wbuf + g * (BT * NWd);
    float* gx = g_xbuf + g * (BT * NXd);

    for (int k = 0; k < NSTEPS; ++k) {
        __syncthreads();  // guards sAct d-part / sPar reuse vs prev e-phase
        // load d_k for the batch tile into act[256:320)
#pragma unroll
        for (int u = 0; u < 4; ++u) {
            int idx = t + u * THREADS;
            int b = idx >> 6, j = idx & 63;
            sAct[b * S_ACT + 256 + j] = dseq[(g * BT + b) * (NSTEPS * NDd) + k * NDd + j];
        }
        __syncthreads();

        // ---- w-phase: w = tanh([C2|D21] . [x|d]), K=320, chunk=20 ----
        {
            int j0 = chunk * 20;
            mm_partial<20, S_W1, 4, 8>(sW1 + row0 * S_W1 + j0,
                                       sAct + b0 * S_ACT + j0,
                                       sPar + chunk * S_PAR + b0 * 33 + row0);
        }
        __syncthreads();
        {
            int o = t * 2;
#pragma unroll
            for (int u = 0; u < 2; ++u) {
                int b = (o + u) >> 5, row = (o + u) & 31;
                float s = 0.f;
#pragma unroll
                for (int c = 0; c < 16; c++) s += sPar[c * S_PAR + b * 33 + row];
                __stcg(&gw[b * NWd + rw + row], tanhf(s));
            }
        }
        cluster_sync_rel();
        // gather full w into act[320:576)
#pragma unroll
        for (int u = 0; u < 16; ++u) {
            int idx = t + u * THREADS;
            int b = idx >> 8, j = idx & 255;
            sAct[b * S_ACT + 320 + j] = __ldcg(&gw[b * NWd + j]);
        }
        __syncthreads();

        // ---- x-phase: x' = [A|B|B2] . [x|d|w], K=576, chunk=36 ----
        {
            int j0 = chunk * 36;
            mm_partial<36, S_W2, 4, 8>(sW2 + row0 * S_W2 + j0,
                                       sAct + b0 * S_ACT + j0,
                                       sPar + chunk * S_PAR + b0 * 33 + row0);
        }
        __syncthreads();
        {
            int o = t * 2;
#pragma unroll
            for (int u = 0; u < 2; ++u) {
                int b = (o + u) >> 5, row = (o + u) & 31;
                float s = 0.f;
#pragma unroll
                for (int c = 0; c < 16; c++) s += sPar[c * S_PAR + b * 33 + row];
                __stcg(&gx[b * NXd + rw + row], s);
            }
        }
        cluster_sync_rel();
        // gather full x_new into act[0:256) (becomes x_{k+1})
#pragma unroll
        for (int u = 0; u < 16; ++u) {
            int idx = t + u * THREADS;
            int b = idx >> 8, j = idx & 255;
            sAct[b * S_ACT + j] = __ldcg(&gx[b * NXd + j]);
        }
        __syncthreads();

        // ---- e-phase: e = [C|D|D12] . [x'|d|w], K=576, chunk=36 ----
        {
            int j0 = chunk * 36;
            mm_partial<36, S_W2, 2, 4>(sW3 + rowe0 * S_W2 + j0,
                                       sAct + be0 * S_ACT + j0,
                                       sPar + chunk * S_PAR + be0 * 33 + rowe0);
        }
        __syncthreads();
        if (t < 128) {
            int b = t >> 3, row = t & 7;
            float s = 0.f;
#pragma unroll
            for (int c = 0; c < 16; c++) s += sPar[c * S_PAR + b * 33 + row];
            out[(g * BT + b) * (NSTEPS * NEd) + k * NEd + re + row] = s;
        }
    }

    __syncthreads();
    // final state outputs: x_final (act x-part), w_{N-1} (act w-part)
#pragma unroll
    for (int u = 0; u < 2; ++u) {
        int idx = t + u * THREADS;
        int b = idx >> 5, row = idx & 31;
        out[BASE_X + (g * BT + b) * NXd + rw + row] = sAct[b * S_ACT + rw + row];
        out[BASE_W + (g * BT + b) * NWd + rw + row] = sAct[b * S_ACT + 320 + rw + row];
    }
}

extern "C" void kernel_launch(void* const* d_in, const int* in_sizes, int n_in,
                              void* d_out, int out_size) {
    (void)in_sizes; (void)n_in; (void)out_size;
    const float* dseq = (const float*)d_in[0];
    const float* x0   = (const float*)d_in[1];
    const float* A    = (const float*)d_in[2];
    const float* B    = (const float*)d_in[3];
    const float* B2   = (const float*)d_in[4];
    const float* C    = (const float*)d_in[5];
    const float* D    = (const float*)d_in[6];
    const float* D12  = (const float*)d_in[7];
    const float* C2   = (const float*)d_in[8];
    const float* D21  = (const float*)d_in[9];
    float* out = (float*)d_out;

    const size_t smem_bytes =
        (size_t)(32 * S_W1 + 32 * S_W2 + 8 * S_W2 + BT * S_ACT + 16 * S_PAR) * sizeof(float);
    cudaFuncSetAttribute(lure_kernel, cudaFuncAttributeMaxDynamicSharedMemorySize,
                         (int)smem_bytes);
    lure_kernel<<<GROUPS * RANKS, THREADS, smem_bytes>>>(dseq, x0, A, B, B2, C, D,
                                                         D12, C2, D21, out);
}

// round 5
// speedup vs baseline: 1.1802x; 1.1802x over previous
#include <cuda_runtime.h>
#include <math.h>

// LureSystem recurrence on GB300 — R4.
// 16 groups x 8-CTA clusters; group g owns batches [16g,16g+16);
// rank r owns rows [32r,32r+32) of w/x and [8r,8r+8) of e.
// Weights TRANSPOSED in SMEM ([K][rows], stride 36) for conflict-free
// float4/u64-packed loads; fma.rn.f32x2 doubles fp32 MAC throughput.
// 512 threads: warp = K-chunk (16 chunks), lane = 4row x 4batch tile.

typedef unsigned long long ull;

#define NXd 256
#define NDd 64
#define NEd 64
#define NWd 256
#define NSTEPS 2048
#define RANKS 8
#define GROUPS 16
#define BT 16
#define THREADS 512

#define S_ACT 580      // [x(256) | d(64) | w(256)] padded; %8==4
#define S_WT 36        // transposed-weight row stride (floats); %8==4
#define S_W3 9         // e-phase transposed-weight stride
#define S_PARC 584     // per-chunk partials stride

#define E_SIZE (256 * NSTEPS * NEd)
#define BASE_X E_SIZE
#define BASE_W (E_SIZE + 256 * NXd)

// SMEM float offsets
#define OFF_W1T 0                         // 320*36 = 11520
#define OFF_W2T 11520                     // 576*36 = 20736
#define OFF_W3T 32256                     // 576*9  = 5184
#define OFF_ACT 37440                     // 16*580 = 9280
#define OFF_PAR 46720                     // 16*584 = 9344
#define SMEM_FLOATS 56064                 // 224256 bytes

__device__ float g_wbuf[GROUPS * BT * NWd];
__device__ float g_xbuf[GROUPS * BT * NXd];

__device__ __forceinline__ void cluster_sync_rel() {
    __threadfence();
    asm volatile("barrier.cluster.arrive.aligned;" ::: "memory");
    asm volatile("barrier.cluster.wait.aligned;" ::: "memory");
}

__device__ __forceinline__ void fma2(ull& acc, ull m, ull a) {
    asm("fma.rn.f32x2 %0, %1, %2, %0;" : "+l"(acc) : "l"(m), "l"(a));
}
__device__ __forceinline__ ull pack2(float x) {
    ull r; asm("mov.b64 %0, {%1, %1};" : "=l"(r) : "f"(x)); return r;
}

// 4 rows x 4 batches over a K-chunk of 4*L4, packed-f32x2 FMAs.
// WT  -> &sWT[j0*S_WT + row0]      (rows row0..row0+3, 16B aligned)
// Act -> &sAct[b0*S_ACT + j0]     (batches b0 + 4*kk)
// P   -> &sPar[chunk*S_PARC + b0*36 + row0]
template <int L4>
__device__ __forceinline__ void mmT(const float* __restrict__ WT,
                                    const float* __restrict__ Act,
                                    float* __restrict__ P) {
    ull acc01[4] = {0ull, 0ull, 0ull, 0ull};
    ull acc23[4] = {0ull, 0ull, 0ull, 0ull};
#pragma unroll
    for (int j4 = 0; j4 < L4; j4++) {
        float a_[4][4];
#pragma unroll
        for (int kk = 0; kk < 4; kk++) {
            float4 t4 = *reinterpret_cast<const float4*>(Act + kk * (4 * S_ACT) + 4 * j4);
            a_[kk][0] = t4.x; a_[kk][1] = t4.y; a_[kk][2] = t4.z; a_[kk][3] = t4.w;
        }
#pragma unroll
        for (int jj = 0; jj < 4; jj++) {
            ulonglong2 m = *reinterpret_cast<const ulonglong2*>(WT + (4 * j4 + jj) * S_WT);
#pragma unroll
            for (int kk = 0; kk < 4; kk++) {
                ull aa = pack2(a_[kk][jj]);
                fma2(acc01[kk], m.x, aa);
                fma2(acc23[kk], m.y, aa);
            }
        }
    }
#pragma unroll
    for (int kk = 0; kk < 4; kk++)
        *reinterpret_cast<ulonglong2*>(P + kk * (4 * 36)) = make_ulonglong2(acc01[kk], acc23[kk]);
}

// e-phase: 1 row x 4 batches, scalar FMAs.
// WT -> &sW3T[j0*S_W3 + row], Act -> &sAct[b0*S_ACT + j0],
// P  -> &sPar[chunk*S_PARC + b0*S_W3 + row]
template <int L4>
__device__ __forceinline__ void mmTe(const float* __restrict__ WT,
                                     const float* __restrict__ Act,
                                     float* __restrict__ P) {
    float acc[4] = {0.f, 0.f, 0.f, 0.f};
#pragma unroll
    for (int j4 = 0; j4 < L4; j4++) {
        float a_[4][4];
#pragma unroll
        for (int kk = 0; kk < 4; kk++) {
            float4 t4 = *reinterpret_cast<const float4*>(Act + kk * (4 * S_ACT) + 4 * j4);
            a_[kk][0] = t4.x; a_[kk][1] = t4.y; a_[kk][2] = t4.z; a_[kk][3] = t4.w;
        }
#pragma unroll
        for (int jj = 0; jj < 4; jj++) {
            float m = WT[(4 * j4 + jj) * S_W3];
#pragma unroll
            for (int kk = 0; kk < 4; kk++) acc[kk] = fmaf(m, a_[kk][jj], acc[kk]);
        }
    }
#pragma unroll
    for (int kk = 0; kk < 4; kk++) P[kk * (4 * S_W3)] = acc[kk];
}

__global__ void __cluster_dims__(RANKS, 1, 1) __launch_bounds__(THREADS, 1)
lure_kernel(const float* __restrict__ dseq,
            const float* __restrict__ x0,
            const float* __restrict__ Amat,
            const float* __restrict__ Bmat,
            const float* __restrict__ B2mat,
            const float* __restrict__ Cmat,
            const float* __restrict__ Dmat,
            const float* __restrict__ D12mat,
            const float* __restrict__ C2mat,
            const float* __restrict__ D21mat,
            float* __restrict__ out) {
    extern __shared__ float smem[];
    float* sW1T = smem + OFF_W1T;   // [320][36] = [C2 | D21]^T rows rw..rw+31
    float* sW2T = smem + OFF_W2T;   // [576][36] = [A | B | B2]^T
    float* sW3T = smem + OFF_W3T;   // [576][9]  = [C | D | D12]^T rows re..re+7
    float* sAct = smem + OFF_ACT;   // [16][580] = [x | d | w]
    float* sPar = smem + OFF_PAR;   // [16][584]

    const int t = threadIdx.x;
    const int g = blockIdx.x >> 3;
    const int r = blockIdx.x & 7;
    const int rw = r * 32;
    const int re = r * 8;

    // ---- load transposed weight slices ----
    for (int idx = t; idx < 320 * 32; idx += THREADS) {
        int row = idx & 31, j = idx >> 5;
        float v = (j < 256) ? C2mat[(rw + row) * NXd + j]
                            : D21mat[(rw + row) * NDd + (j - 256)];
        sW1T[j * S_WT + row] = v;
    }
    for (int idx = t; idx < 576 * 32; idx += THREADS) {
        int row = idx & 31, j = idx >> 5;
        float v;
        if (j < 256)      v = Amat[(rw + row) * NXd + j];
        else if (j < 320) v = Bmat[(rw + row) * NDd + (j - 256)];
        else              v = B2mat[(rw + row) * NWd + (j - 320)];
        sW2T[j * S_WT + row] = v;
    }
    for (int idx = t; idx < 576 * 8; idx += THREADS) {
        int row = idx & 7, j = idx >> 3;
        float v;
        if (j < 256)      v = Cmat[(re + row) * NXd + j];
        else if (j < 320) v = Dmat[(re + row) * NDd + (j - 256)];
        else              v = D12mat[(re + row) * NWd + (j - 320)];
        sW3T[j * S_W3 + row] = v;
    }
    // x0 and d_0
    for (int idx = t; idx < BT * 256; idx += THREADS) {
        int b = idx >> 8, col = idx & 255;
        sAct[b * S_ACT + col] = x0[(g * BT + b) * NXd + col];
    }
#pragma unroll
    for (int u = 0; u < 2; ++u) {
        int idx = t + u * THREADS;
        int b = idx >> 6, j = idx & 63;
        sAct[b * S_ACT + 256 + j] = dseq[(size_t)(g * BT + b) * (NSTEPS * NDd) + j];
    }

    // work decomposition: warp = K-chunk, lane = tile
    const int lane = t & 31, warp = t >> 5;
    const int row0 = (lane & 7) * 4;    // w/x rows
    const int b0 = lane >> 3;           // batches b0 + 4*kk
    const int rowe = lane & 7;          // e row
    const int j0w = warp * 20;
    const int j0x = warp * 36;

    float* gw = g_wbuf + g * (BT * NWd);
    float* gx = g_xbuf + g * (BT * NXd);

    // reduction mapping
    const int rb = t >> 5, rr = t & 31;       // w/x outputs (512)
    const int eb = t >> 3, er = t & 7;        // e outputs (128, t<128)

    float dpre[2];

    for (int k = 0; k < NSTEPS; ++k) {
        __syncthreads();  // sPar reuse + d commit visible

        // prefetch d_{k+1}
        int kp = (k + 1 < NSTEPS) ? (k + 1) : (NSTEPS - 1);
#pragma unroll
        for (int u = 0; u < 2; ++u) {
            int idx = t + u * THREADS;
            int b = idx >> 6, j = idx & 63;
            dpre[u] = dseq[(size_t)(g * BT + b) * (NSTEPS * NDd) + kp * NDd + j];
        }

        // ---- w-phase: K=320, chunk=20 ----
        mmT<5>(sW1T + j0w * S_WT + row0,
               sAct + b0 * S_ACT + j0w,
               sPar + warp * S_PARC + b0 * 36 + row0);
        __syncthreads();
        {
            float s = 0.f;
#pragma unroll
            for (int c = 0; c < 16; c++) s += sPar[c * S_PARC + rb * 36 + rr];
            __stcg(&gw[rb * NWd + rw + rr], tanhf(s));
        }
        cluster_sync_rel();
#pragma unroll
        for (int u = 0; u < 8; ++u) {
            int idx = t + u * THREADS;
            int b = idx >> 8, j = idx & 255;
            sAct[b * S_ACT + 320 + j] = __ldcg(&gw[b * NWd + j]);
        }
        __syncthreads();

        // ---- x-phase: K=576, chunk=36 ----
        mmT<9>(sW2T + j0x * S_WT + row0,
               sAct + b0 * S_ACT + j0x,
               sPar + warp * S_PARC + b0 * 36 + row0);
        __syncthreads();
        {
            float s = 0.f;
#pragma unroll
            for (int c = 0; c < 16; c++) s += sPar[c * S_PARC + rb * 36 + rr];
            __stcg(&gx[rb * NXd + rw + rr], s);
        }
        cluster_sync_rel();
#pragma unroll
        for (int u = 0; u < 8; ++u) {
            int idx = t + u * THREADS;
            int b = idx >> 8, j = idx & 255;
            sAct[b * S_ACT + j] = __ldcg(&gx[b * NXd + j]);
        }
        __syncthreads();

        // ---- e-phase: K=576, chunk=36 ----
        mmTe<9>(sW3T + j0x * S_W3 + rowe,
                sAct + b0 * S_ACT + j0x,
                sPar + warp * S_PARC + b0 * S_W3 + rowe);
        __syncthreads();

        // commit prefetched d_{k+1} (region free after e-phase reads)
#pragma unroll
        for (int u = 0; u < 2; ++u) {
            int idx = t + u * THREADS;
            int b = idx >> 6, j = idx & 63;
            sAct[b * S_ACT + 256 + j] = dpre[u];
        }

        if (t < 128) {
            float s = 0.f;
#pragma unroll
            for (int c = 0; c < 16; c++) s += sPar[c * S_PARC + eb * S_W3 + er];
            out[(size_t)(g * BT + eb) * (NSTEPS * NEd) + k * NEd + re + er] = s;
        }
    }

    __syncthreads();
    // final state outputs
    {
        int b = t >> 5, row = t & 31;
        out[BASE_X + (size_t)(g * BT + b) * NXd + rw + row] = sAct[b * S_ACT + rw + row];
        out[BASE_W + (size_t)(g * BT + b) * NWd + rw + row] = sAct[b * S_ACT + 320 + rw + row];
    }
}

extern "C" void kernel_launch(void* const* d_in, const int* in_sizes, int n_in,
                              void* d_out, int out_size) {
    (void)in_sizes; (void)n_in; (void)out_size;
    const float* dseq = (const float*)d_in[0];
    const float* x0   = (const float*)d_in[1];
    const float* A    = (const float*)d_in[2];
    const float* B    = (const float*)d_in[3];
    const float* B2   = (const float*)d_in[4];
    const float* C    = (const float*)d_in[5];
    const float* D    = (const float*)d_in[6];
    const float* D12  = (const float*)d_in[7];
    const float* C2   = (const float*)d_in[8];
    const float* D21  = (const float*)d_in[9];
    float* out = (float*)d_out;

    const size_t smem_bytes = (size_t)SMEM_FLOATS * sizeof(float);
    cudaFuncSetAttribute(lure_kernel, cudaFuncAttributeMaxDynamicSharedMemorySize,
                         (int)smem_bytes);
    lure_kernel<<<GROUPS * RANKS, THREADS, smem_bytes>>>(dseq, x0, A, B, B2, C, D,
                                                         D12, C2, D21, out);
}

// round 6
// speedup vs baseline: 1.2242x; 1.0373x over previous
#include <cuda_runtime.h>
#include <math.h>

typedef unsigned long long ull;

// LureSystem on GB300 — R5.
// Fused e-phase: e = (C@A)x + (C@B+D)d + (C@B2+D12)w shares act vector with
// x-update -> one 40-row mm. 16 groups x 8-CTA clusters, 640 threads.
// Exchange via L2 st.cg/ld.cg + barrier.cluster (release/acquire, no fence).

#define NSTEPS 2048
#define RANKS 8
#define GROUPS 16
#define BT 16
#define THREADS 640

#define S_ACT 584           // [x(256)|d(64)|w(256)] padded; %32==8 -> btile banks 8*bt
#define PARW 576            // w-phase per-chunk partial stride (16*36)
#define PARX 704            // xe-phase per-chunk partial stride (16*44)

// SMEM float offsets
#define OFF_W1T 0           // [320][32]  [C2|D21]^T rows rw..rw+31
#define OFF_W2T 10240       // [576][40]  rows 0-31: [A|B|B2]^T ; rows 32-39: fused E^T
#define OFF_ACT 33280       // [16][584]
#define OFF_PAR 42624       // max(20*576, 16*704) = 11520
#define SMEM_FLOATS 54144   // 216576 bytes

#define E_SIZE (256 * NSTEPS * 64)
#define BASE_X E_SIZE
#define BASE_W (E_SIZE + 256 * 256)

__device__ float g_EW[64 * 576];             // fused e-weights [row][ x|d|w cols ]
__device__ float g_wbuf[GROUPS * BT * 256];
__device__ float g_xbuf[GROUPS * BT * 256];

__device__ __forceinline__ void cluster_sync() {
    // arrive defaults to .release, wait to .acquire: orders st.cg -> ld.cg in cluster
    asm volatile("barrier.cluster.arrive.aligned;" ::: "memory");
    asm volatile("barrier.cluster.wait.aligned;" ::: "memory");
}

__device__ __forceinline__ void fma2(ull& acc, ull m, ull a) {
    asm("fma.rn.f32x2 %0, %1, %2, %0;" : "+l"(acc) : "l"(m), "l"(a));
}
__device__ __forceinline__ ull pack2(float x) {
    ull r; asm("mov.b64 %0, {%1, %1};" : "=l"(r) : "f"(x)); return r;
}

// 4 rows x 4 batches (b = btile + 4*kk) over K-chunk of 4*L4, f32x2 FMAs.
template <int L4, int WS, int BS>
__device__ __forceinline__ void mmT(const float* __restrict__ WT,
                                    const float* __restrict__ Act,
                                    float* __restrict__ P) {
    ull a01[4] = {0ull, 0ull, 0ull, 0ull};
    ull a23[4] = {0ull, 0ull, 0ull, 0ull};
#pragma unroll
    for (int j4 = 0; j4 < L4; j4++) {
        float av[4][4];
#pragma unroll
        for (int kk = 0; kk < 4; kk++) {
            float4 t4 = *reinterpret_cast<const float4*>(Act + kk * (4 * S_ACT) + 4 * j4);
            av[kk][0] = t4.x; av[kk][1] = t4.y; av[kk][2] = t4.z; av[kk][3] = t4.w;
        }
#pragma unroll
        for (int jj = 0; jj < 4; jj++) {
            ulonglong2 m = *reinterpret_cast<const ulonglong2*>(WT + (4 * j4 + jj) * WS);
#pragma unroll
            for (int kk = 0; kk < 4; kk++) {
                ull aa = pack2(av[kk][jj]);
                fma2(a01[kk], m.x, aa);
                fma2(a23[kk], m.y, aa);
            }
        }
    }
#pragma unroll
    for (int kk = 0; kk < 4; kk++)
        *reinterpret_cast<ulonglong2*>(P + kk * (4 * BS)) = make_ulonglong2(a01[kk], a23[kk]);
}

// ---- pre-kernel: build fused e-weights EW = [C@A | C@B + D | C@B2 + D12] ----
__global__ void fuse_kernel(const float* __restrict__ A, const float* __restrict__ B,
                            const float* __restrict__ B2, const float* __restrict__ C,
                            const float* __restrict__ D, const float* __restrict__ D12) {
    __shared__ float c[256];
    int i = blockIdx.x;
    for (int idx = threadIdx.x; idx < 256; idx += blockDim.x) c[idx] = C[i * 256 + idx];
    __syncthreads();
    for (int j = threadIdx.x; j < 576; j += blockDim.x) {
        float s = 0.f;
        if (j < 256) {
            for (int kk = 0; kk < 256; kk++) s = fmaf(c[kk], A[kk * 256 + j], s);
        } else if (j < 320) {
            int jj = j - 256;
            for (int kk = 0; kk < 256; kk++) s = fmaf(c[kk], B[kk * 64 + jj], s);
            s += D[i * 64 + jj];
        } else {
            int jj = j - 320;
            for (int kk = 0; kk < 256; kk++) s = fmaf(c[kk], B2[kk * 256 + jj], s);
            s += D12[i * 256 + jj];
        }
        g_EW[i * 576 + j] = s;
    }
}

__global__ void __cluster_dims__(RANKS, 1, 1) __launch_bounds__(THREADS, 1)
lure_kernel(const float* __restrict__ dseq,
            const float* __restrict__ x0,
            const float* __restrict__ Amat,
            const float* __restrict__ Bmat,
            const float* __restrict__ B2mat,
            const float* __restrict__ C2mat,
            const float* __restrict__ D21mat,
            float* __restrict__ out) {
    extern __shared__ float smem[];
    float* sW1T = smem + OFF_W1T;
    float* sW2T = smem + OFF_W2T;
    float* sAct = smem + OFF_ACT;
    float* sPar = smem + OFF_PAR;

    const int t = threadIdx.x;
    const int g = blockIdx.x >> 3;
    const int r = blockIdx.x & 7;
    const int rw = r * 32;
    const int re = r * 8;

    // ---- resident weights (transposed [K][row]) ----
    for (int idx = t; idx < 320 * 32; idx += THREADS) {
        int row = idx & 31, j = idx >> 5;
        float v = (j < 256) ? C2mat[(rw + row) * 256 + j]
                            : D21mat[(rw + row) * 64 + (j - 256)];
        sW1T[j * 32 + row] = v;
    }
    for (int idx = t; idx < 576 * 40; idx += THREADS) {
        int row = idx % 40, j = idx / 40;
        float v;
        if (row < 32) {
            int gr = rw + row;
            if (j < 256)      v = Amat[gr * 256 + j];
            else if (j < 320) v = Bmat[gr * 64 + (j - 256)];
            else              v = B2mat[gr * 256 + (j - 320)];
        } else {
            v = g_EW[(re + row - 32) * 576 + j];
        }
        sW2T[j * 40 + row] = v;
    }
    for (int idx = t; idx < BT * 256; idx += THREADS) {
        int b = idx >> 8, col = idx & 255;
        sAct[b * S_ACT + col] = x0[(g * BT + b) * 256 + col];
    }
    for (int idx = t; idx < BT * 64; idx += THREADS) {
        int b = idx >> 6, j = idx & 63;
        sAct[b * S_ACT + 256 + j] = dseq[(size_t)(g * BT + b) * (NSTEPS * 64) + j];
    }

    // work decomposition
    const int lane = t & 31, warp = t >> 5;
    const int btw = lane >> 3, row0w = (lane & 7) * 4, j0w = warp * 16;   // w-phase
    const int tl = t % 40, chunkx = t / 40;
    const int btx = tl / 10, row0x = (tl % 10) * 4, j0x = chunkx * 36;    // xe-phase
    const int rb = t >> 5, rr = t & 31;          // w reduce (t<512)
    const int xb = t / 40, xr = t % 40;          // xe reduce

    float* gw = g_wbuf + g * (BT * 256);
    float* gx = g_xbuf + g * (BT * 256);

    float dpre0, dpre1;
    const int d0b = t >> 6, d0j = t & 63;
    const int i1 = t + 640;
    const int d1b = i1 >> 6, d1j = i1 & 63;

    __syncthreads();

    for (int k = 0; k < NSTEPS; ++k) {
        // prefetch d_{k+1}
        int kp = (k + 1 < NSTEPS) ? (k + 1) : (NSTEPS - 1);
        dpre0 = dseq[(size_t)(g * BT + d0b) * (NSTEPS * 64) + (size_t)kp * 64 + d0j];
        if (i1 < 1024)
            dpre1 = dseq[(size_t)(g * BT + d1b) * (NSTEPS * 64) + (size_t)kp * 64 + d1j];

        // ---- w-phase: 32 rows, K=320, chunk=warp (20 x 16) ----
        mmT<4, 32, 36>(sW1T + j0w * 32 + row0w,
                       sAct + btw * S_ACT + j0w,
                       sPar + warp * PARW + btw * 36 + row0w);
        __syncthreads();
        if (t < 512) {
            float s = 0.f;
#pragma unroll
            for (int c = 0; c < 20; c++) s += sPar[c * PARW + rb * 36 + rr];
            __stcg(&gw[rb * 256 + rw + rr], tanhf(s));
        }
        cluster_sync();
#pragma unroll
        for (int u = 0; u < 7; ++u) {
            int idx = t + u * THREADS;
            if (idx < 4096) {
                int b = idx >> 8, j = idx & 255;
                sAct[b * S_ACT + 320 + j] = __ldcg(&gw[b * 256 + j]);
            }
        }
        __syncthreads();

        // ---- xe-phase: 40 rows (32 x' + 8 e), K=576, 16 chunks x 36 ----
        mmT<9, 40, 44>(sW2T + j0x * 40 + row0x,
                       sAct + btx * S_ACT + j0x,
                       sPar + chunkx * PARX + btx * 44 + row0x);
        __syncthreads();
        {
            float s = 0.f;
#pragma unroll
            for (int c = 0; c < 16; c++) s += sPar[c * PARX + xb * 44 + xr];
            if (xr < 32)
                __stcg(&gx[xb * 256 + rw + xr], s);
            else
                out[(size_t)(g * BT + xb) * (NSTEPS * 64) + (size_t)k * 64 + re + (xr - 32)] = s;
            // commit prefetched d_{k+1} (d region free after xe-mm barrier)
            sAct[d0b * S_ACT + 256 + d0j] = dpre0;
            if (i1 < 1024) sAct[d1b * S_ACT + 256 + d1j] = dpre1;
        }
        cluster_sync();
#pragma unroll
        for (int u = 0; u < 7; ++u) {
            int idx = t + u * THREADS;
            if (idx < 4096) {
                int b = idx >> 8, j = idx & 255;
                sAct[b * S_ACT + j] = __ldcg(&gx[b * 256 + j]);
            }
        }
        __syncthreads();
    }

    // final states: x_final from act x-part, w_{N-1} from act w-part
    if (t < 512) {
        int b = t >> 5, row = t & 31;
        out[BASE_X + (size_t)(g * BT + b) * 256 + rw + row] = sAct[b * S_ACT + rw + row];
        out[BASE_W + (size_t)(g * BT + b) * 256 + rw + row] = sAct[b * S_ACT + 320 + rw + row];
    }
}

extern "C" void kernel_launch(void* const* d_in, const int* in_sizes, int n_in,
                              void* d_out, int out_size) {
    (void)in_sizes; (void)n_in; (void)out_size;
    const float* dseq = (const float*)d_in[0];
    const float* x0   = (const float*)d_in[1];
    const float* A    = (const float*)d_in[2];
    const float* B    = (const float*)d_in[3];
    const float* B2   = (const float*)d_in[4];
    const float* C    = (const float*)d_in[5];
    const float* D    = (const float*)d_in[6];
    const float* D12  = (const float*)d_in[7];
    const float* C2   = (const float*)d_in[8];
    const float* D21  = (const float*)d_in[9];
    float* out = (float*)d_out;

    fuse_kernel<<<64, 256>>>(A, B, B2, C, D, D12);

    const size_t smem_bytes = (size_t)SMEM_FLOATS * sizeof(float);
    cudaFuncSetAttribute(lure_kernel, cudaFuncAttributeMaxDynamicSharedMemorySize,
                         (int)smem_bytes);
    lure_kernel<<<GROUPS * RANKS, THREADS, smem_bytes>>>(dseq, x0, A, B, B2,
                                                         C2, D21, out);
}